// round 7
// baseline (speedup 1.0000x reference)
#include <cuda_runtime.h>
#include <cstdint>

// ---------------------------------------------------------------------------
// GCN layer: out = relu( D_in^-1/2 · A · D_out^-1/2 · (X @ W) + b )
// N=100000, E=1600000, IN=256, OUT=32  (fp32, src/dst int32)
//
// 5-node graph (no memsets — kernels restore the zero-state invariant):
//   deg -> +-> gemm (side, zeroes outdeg after use) -+-> agg (zeroes indeg)
//          +-> scan (resets ctr) -> fill ------------+
// ---------------------------------------------------------------------------

#define NMAX 100000
#define EMAX 1600000
#define IN_F 256
#define OUT_F 32
#define SCAN_BLK 512
#define SCAN_SHIFT 9
#define SCAN_NBLK ((NMAX + SCAN_BLK - 1) / SCAN_BLK)   // 196

#define TILE_R 64
#define FP_STRIDE 33
#define GEMM_SMEM (IN_F * OUT_F * 4 + IN_F * FP_STRIDE * 8)   // 98KB

// zero-initialized at module load; every replay restores zeros where needed
__device__ unsigned g_outdeg[NMAX];
__device__ unsigned g_indeg[NMAX];
__device__ unsigned g_off[NMAX];
__device__ unsigned g_bsum[SCAN_NBLK];
__device__ unsigned g_scan_ctr;
__device__ int      g_esrc[EMAX];
__device__ __align__(16) float g_h[(size_t)NMAX * OUT_F];

// packed f32x2 helpers -------------------------------------------------------
#define FMA_F32X2(acc, a, b) \
    asm("fma.rn.f32x2 %0, %1, %2, %0;" : "+l"(acc) : "l"(a), "l"(b))
#define PACK_DUP_F32X2(out, w) \
    asm("mov.b64 %0, {%1, %1};" : "=l"(out) : "f"(w))
#define UNPACK_F32X2(lo, hi, in) \
    asm("mov.b64 {%0, %1}, %2;" : "=f"(lo), "=f"(hi) : "l"(in))

// ---------------------------------------------------------------------------
// Degrees: 4 edges per thread via int4 loads on both arrays.
__global__ void k_deg(const int* __restrict__ src,
                      const int* __restrict__ dst, int E) {
    int i = blockIdx.x * blockDim.x + threadIdx.x;
    int base = i * 4;
    if (base + 3 < E) {
        int4 s = ((const int4*)src)[i];
        int4 d = ((const int4*)dst)[i];
        atomicAdd(&g_outdeg[s.x], 1u);
        atomicAdd(&g_outdeg[s.y], 1u);
        atomicAdd(&g_outdeg[s.z], 1u);
        atomicAdd(&g_outdeg[s.w], 1u);
        atomicAdd(&g_indeg[d.x], 1u);
        atomicAdd(&g_indeg[d.y], 1u);
        atomicAdd(&g_indeg[d.z], 1u);
        atomicAdd(&g_indeg[d.w], 1u);
    } else {
        for (int j = base; j < E; ++j) {
            atomicAdd(&g_outdeg[src[j]], 1u);
            atomicAdd(&g_indeg[dst[j]], 1u);
        }
    }
}

// ---------------------------------------------------------------------------
// Single-pass two-level scan; last block aggregates g_bsum and resets ctr.
__global__ void k_scan(int n_nodes) {
    __shared__ unsigned s[SCAN_BLK];
    __shared__ bool is_last;
    int t = threadIdx.x;
    int i = blockIdx.x * SCAN_BLK + t;
    unsigned v = (i < n_nodes) ? g_indeg[i] : 0u;
    s[t] = v;
    __syncthreads();
    for (int off = 1; off < SCAN_BLK; off <<= 1) {
        unsigned x = (t >= off) ? s[t - off] : 0u;
        __syncthreads();
        s[t] += x;
        __syncthreads();
    }
    if (i < n_nodes) g_off[i] = s[t] - v;          // block-local exclusive
    if (t == SCAN_BLK - 1) g_bsum[blockIdx.x] = s[t];

    __threadfence();
    if (t == 0) {
        unsigned done = atomicAdd(&g_scan_ctr, 1u);
        is_last = (done == (unsigned)(gridDim.x - 1));
    }
    __syncthreads();
    if (is_last) {
        __threadfence();
        if (t == 0) g_scan_ctr = 0u;               // restore invariant
        unsigned bv = (t < SCAN_NBLK) ? g_bsum[t] : 0u;
        s[t] = bv;
        __syncthreads();
        for (int off = 1; off < 256; off <<= 1) {
            unsigned x = (t >= off && t < 256) ? s[t - off] : 0u;
            __syncthreads();
            if (t < 256) s[t] += x;
            __syncthreads();
        }
        if (t < SCAN_NBLK) g_bsum[t] = s[t] - bv;  // exclusive block sums
    }
}

// ---------------------------------------------------------------------------
// CSR fill: cursor fused into g_off (atomic bump), 4 edges per thread.
__global__ void k_fill(const int* __restrict__ src,
                       const int* __restrict__ dst, int E) {
    int i = blockIdx.x * blockDim.x + threadIdx.x;
    int base = i * 4;
    if (base + 3 < E) {
        int4 s = ((const int4*)src)[i];
        int4 d = ((const int4*)dst)[i];
        unsigned p0 = atomicAdd(&g_off[d.x], 1u) + g_bsum[d.x >> SCAN_SHIFT];
        unsigned p1 = atomicAdd(&g_off[d.y], 1u) + g_bsum[d.y >> SCAN_SHIFT];
        unsigned p2 = atomicAdd(&g_off[d.z], 1u) + g_bsum[d.z >> SCAN_SHIFT];
        unsigned p3 = atomicAdd(&g_off[d.w], 1u) + g_bsum[d.w >> SCAN_SHIFT];
        g_esrc[p0] = s.x;
        g_esrc[p1] = s.y;
        g_esrc[p2] = s.z;
        g_esrc[p3] = s.w;
    } else {
        for (int j = base; j < E; ++j) {
            int d = dst[j];
            unsigned pos = atomicAdd(&g_off[d], 1u) + g_bsum[d >> SCAN_SHIFT];
            g_esrc[pos] = src[j];
        }
    }
}

// ---------------------------------------------------------------------------
// GEMM with packed f32x2 FMA. 256 threads, 64-row tile, 98KB dynamic smem.
// Epilogue zeroes g_outdeg (restores invariant for next replay).
__global__ void __launch_bounds__(256, 2)
k_gemm(const float* __restrict__ feat, const float* __restrict__ W,
       int n_nodes) {
    extern __shared__ float smem[];
    float* sW = smem;                                    // [256][32]
    float* sFPf = smem + IN_F * OUT_F;                   // [256 k][66 floats]
    unsigned long long* sFPu = (unsigned long long*)sFPf;

    const int tid  = threadIdx.x;
    const int lane = tid & 31;
    const int warp = tid >> 5;
    const int row0 = blockIdx.x * TILE_R;

    for (int i = tid; i < (IN_F * OUT_F) / 4; i += 256)
        ((float4*)sW)[i] = ((const float4*)W)[i];

    // transpose-load feat tile (coalesced LDG.32, 2-way-conflict STS)
    for (int it = 0; it < TILE_R; ++it) {
        int idx = tid + 256 * it;          // idx = r_local*256 + k
        int rl = idx >> 8;
        int k  = idx & 255;
        int row = row0 + rl;
        float v = (row < n_nodes) ? feat[(size_t)row * IN_F + k] : 0.f;
        sFPf[k * (2 * FP_STRIDE) + rl] = v;
    }
    __syncthreads();

    unsigned long long acc[4];
    acc[0] = acc[1] = acc[2] = acc[3] = 0ull;
    const int pbase = warp * 4;                 // 4 row-pairs per warp

    for (int kc = 0; kc < IN_F / 32; ++kc) {
        unsigned long long w2[32];
        #pragma unroll
        for (int kk = 0; kk < 32; ++kk) {
            float w = sW[(kc * 32 + kk) * OUT_F + lane];
            PACK_DUP_F32X2(w2[kk], w);
        }
        #pragma unroll
        for (int rp = 0; rp < 4; ++rp) {
            const unsigned long long* f = &sFPu[(size_t)(kc * 32) * FP_STRIDE
                                                + pbase + rp];
            #pragma unroll
            for (int kk = 0; kk < 32; ++kk) {
                unsigned long long f2 = f[kk * FP_STRIDE];   // LDS.b64 bcast
                FMA_F32X2(acc[rp], f2, w2[kk]);
            }
        }
    }

    #pragma unroll
    for (int rp = 0; rp < 4; ++rp) {
        float a0, a1;
        UNPACK_F32X2(a0, a1, acc[rp]);
        int r0 = row0 + (pbase + rp) * 2;
        if (r0 < n_nodes) {
            unsigned d = g_outdeg[r0];
            g_h[(size_t)r0 * OUT_F + lane] = a0 * rsqrtf((float)(d ? d : 1u));
            if (lane == 0) g_outdeg[r0] = 0u;              // restore invariant
        }
        if (r0 + 1 < n_nodes) {
            unsigned d = g_outdeg[r0 + 1];
            g_h[(size_t)(r0 + 1) * OUT_F + lane] =
                a1 * rsqrtf((float)(d ? d : 1u));
            if (lane == 0) g_outdeg[r0 + 1] = 0u;          // restore invariant
        }
    }
}

// ---------------------------------------------------------------------------
// Aggregation: warp per destination node, lane = output column.
// Zeroes g_indeg after use (restores invariant).
__global__ void k_agg(float* __restrict__ out,
                      const float* __restrict__ bias, int n_nodes) {
    int warp = (blockIdx.x * blockDim.x + threadIdx.x) >> 5;
    int lane = threadIdx.x & 31;
    if (warp >= n_nodes) return;

    unsigned deg = g_indeg[warp];
    unsigned off = g_off[warp] + g_bsum[warp >> SCAN_SHIFT] - deg;
    if (lane == 0) g_indeg[warp] = 0u;                     // restore invariant

    float acc0 = 0.f, acc1 = 0.f;
    for (unsigned c = 0; c < deg; c += 32) {
        unsigned rem = deg - c;
        unsigned cnt = rem < 32u ? rem : 32u;
        int e = (lane < cnt) ? g_esrc[off + c + lane] : 0;
        unsigned j = 0;
        for (; j + 2 <= cnt; j += 2) {
            int s0 = __shfl_sync(0xFFFFFFFFu, e, j);
            int s1 = __shfl_sync(0xFFFFFFFFu, e, j + 1);
            acc0 += g_h[(size_t)s0 * OUT_F + lane];
            acc1 += g_h[(size_t)s1 * OUT_F + lane];
        }
        if (j < cnt) {
            int s0 = __shfl_sync(0xFFFFFFFFu, e, j);
            acc0 += g_h[(size_t)s0 * OUT_F + lane];
        }
    }

    float sc = rsqrtf((float)(deg ? deg : 1u));
    float v = fmaf(acc0 + acc1, sc, bias[lane]);
    out[(size_t)warp * OUT_F + lane] = fmaxf(v, 0.f);
}

// ---------------------------------------------------------------------------
extern "C" void kernel_launch(void* const* d_in, const int* in_sizes, int n_in,
                              void* d_out, int out_size) {
    const float* feat = (const float*)d_in[0];
    const int*   src  = (const int*)d_in[1];
    const int*   dst  = (const int*)d_in[2];
    const float* W    = (const float*)d_in[3];
    const float* bias = (const float*)d_in[4];
    float* out = (float*)d_out;

    const int N = in_sizes[0] / IN_F;
    const int E = in_sizes[1];
    const int nth4 = (E + 3) / 4;

    cudaFuncSetAttribute(k_gemm, cudaFuncAttributeMaxDynamicSharedMemorySize,
                         GEMM_SMEM);

    // host-only objects (no device memory)
    cudaStream_t side;
    cudaEvent_t ev_fork, ev_join;
    cudaStreamCreateWithFlags(&side, cudaStreamNonBlocking);
    cudaEventCreateWithFlags(&ev_fork, cudaEventDisableTiming);
    cudaEventCreateWithFlags(&ev_join, cudaEventDisableTiming);

    // main: degrees for both endpoints
    k_deg<<<(nth4 + 255) / 256, 256>>>(src, dst, E);

    // fork: gemm depends only on g_outdeg
    cudaEventRecord(ev_fork, 0);
    cudaStreamWaitEvent(side, ev_fork, 0);
    k_gemm<<<(N + TILE_R - 1) / TILE_R, 256, GEMM_SMEM, side>>>(feat, W, N);
    cudaEventRecord(ev_join, side);

    // main: CSR build
    k_scan<<<SCAN_NBLK, SCAN_BLK>>>(N);
    k_fill<<<(nth4 + 255) / 256, 256>>>(src, dst, E);

    // join, aggregate
    cudaStreamWaitEvent(0, ev_join, 0);
    k_agg<<<(N * 32 + 255) / 256, 256>>>(out, bias, N);
}

// round 8
// speedup vs baseline: 1.0126x; 1.0126x over previous
#include <cuda_runtime.h>
#include <cstdint>

// ---------------------------------------------------------------------------
// GCN layer: out = relu( D_in^-1/2 · A · D_out^-1/2 · (X @ W) + b )
// N=100000, E=1600000, IN=256, OUT=32  (fp32, src/dst int32)
//
// 5-node graph; gemm has NO dependencies (out-degree scaling moved to agg):
//   side: gemm (t=0) ------------------------------+
//   main: deg -> scan(+scale, zero outdeg) -> fill -+-> agg (zero indeg)
// ---------------------------------------------------------------------------

#define NMAX 100000
#define EMAX 1600000
#define IN_F 256
#define OUT_F 32
#define SCAN_BLK 512
#define SCAN_SHIFT 9
#define SCAN_NBLK ((NMAX + SCAN_BLK - 1) / SCAN_BLK)   // 196

#define TILE_R 64
#define FP_STRIDE 33
#define GEMM_SMEM (IN_F * OUT_F * 4 + IN_F * FP_STRIDE * 8)   // 98KB

// zero at module load; kernels restore zeros they consume (see comments)
__device__ unsigned g_outdeg[NMAX];
__device__ unsigned g_indeg[NMAX];
__device__ unsigned g_off[NMAX];
__device__ unsigned g_bsum[SCAN_NBLK];
__device__ unsigned g_scan_ctr;
__device__ float    g_scale[NMAX];          // outdeg^-1/2
__device__ int      g_esrc[EMAX];
__device__ __align__(16) float g_h[(size_t)NMAX * OUT_F];

// packed f32x2 helpers -------------------------------------------------------
#define FMA_F32X2(acc, a, b) \
    asm("fma.rn.f32x2 %0, %1, %2, %0;" : "+l"(acc) : "l"(a), "l"(b))
#define PACK_DUP_F32X2(out, w) \
    asm("mov.b64 %0, {%1, %1};" : "=l"(out) : "f"(w))
#define UNPACK_F32X2(lo, hi, in) \
    asm("mov.b64 {%0, %1}, %2;" : "=f"(lo), "=f"(hi) : "l"(in))

// ---------------------------------------------------------------------------
// Degrees: 1 edge per thread (max TLP for latency-bound REDs).
__global__ void k_deg(const int* __restrict__ src,
                      const int* __restrict__ dst, int E) {
    int i = blockIdx.x * blockDim.x + threadIdx.x;
    if (i < E) {
        atomicAdd(&g_outdeg[src[i]], 1u);
        atomicAdd(&g_indeg[dst[i]], 1u);
    }
}

// ---------------------------------------------------------------------------
// Single-pass two-level scan of in_deg; also converts out_deg -> scale and
// zeroes out_deg (invariant restore). Last block aggregates g_bsum + resets ctr.
__global__ void k_scan(int n_nodes) {
    __shared__ unsigned s[SCAN_BLK];
    __shared__ bool is_last;
    int t = threadIdx.x;
    int i = blockIdx.x * SCAN_BLK + t;

    if (i < n_nodes) {
        unsigned od = g_outdeg[i];
        g_scale[i] = rsqrtf((float)(od ? od : 1u));
        g_outdeg[i] = 0u;                              // restore invariant
    }

    unsigned v = (i < n_nodes) ? g_indeg[i] : 0u;
    s[t] = v;
    __syncthreads();
    for (int off = 1; off < SCAN_BLK; off <<= 1) {
        unsigned x = (t >= off) ? s[t - off] : 0u;
        __syncthreads();
        s[t] += x;
        __syncthreads();
    }
    if (i < n_nodes) g_off[i] = s[t] - v;              // block-local exclusive
    if (t == SCAN_BLK - 1) g_bsum[blockIdx.x] = s[t];

    __threadfence();
    if (t == 0) {
        unsigned done = atomicAdd(&g_scan_ctr, 1u);
        is_last = (done == (unsigned)(gridDim.x - 1));
    }
    __syncthreads();
    if (is_last) {
        __threadfence();
        if (t == 0) g_scan_ctr = 0u;                   // restore invariant
        unsigned bv = (t < SCAN_NBLK) ? g_bsum[t] : 0u;
        s[t] = bv;
        __syncthreads();
        for (int off = 1; off < 256; off <<= 1) {
            unsigned x = (t >= off && t < 256) ? s[t - off] : 0u;
            __syncthreads();
            if (t < 256) s[t] += x;
            __syncthreads();
        }
        if (t < SCAN_NBLK) g_bsum[t] = s[t] - bv;      // exclusive block sums
    }
}

// ---------------------------------------------------------------------------
// CSR fill: 1 edge per thread, cursor fused into g_off (atomic bump).
__global__ void k_fill(const int* __restrict__ src,
                       const int* __restrict__ dst, int E) {
    int i = blockIdx.x * blockDim.x + threadIdx.x;
    if (i < E) {
        int d = dst[i];
        unsigned pos = atomicAdd(&g_off[d], 1u) + g_bsum[d >> SCAN_SHIFT];
        g_esrc[pos] = src[i];
    }
}

// ---------------------------------------------------------------------------
// GEMM with packed f32x2 FMA. NO degree dependency: stores raw X@W.
__global__ void __launch_bounds__(256, 2)
k_gemm(const float* __restrict__ feat, const float* __restrict__ W,
       int n_nodes) {
    extern __shared__ float smem[];
    float* sW = smem;                                    // [256][32]
    float* sFPf = smem + IN_F * OUT_F;                   // [256 k][66 floats]
    unsigned long long* sFPu = (unsigned long long*)sFPf;

    const int tid  = threadIdx.x;
    const int lane = tid & 31;
    const int warp = tid >> 5;
    const int row0 = blockIdx.x * TILE_R;

    for (int i = tid; i < (IN_F * OUT_F) / 4; i += 256)
        ((float4*)sW)[i] = ((const float4*)W)[i];

    for (int it = 0; it < TILE_R; ++it) {
        int idx = tid + 256 * it;          // idx = r_local*256 + k
        int rl = idx >> 8;
        int k  = idx & 255;
        int row = row0 + rl;
        float v = (row < n_nodes) ? feat[(size_t)row * IN_F + k] : 0.f;
        sFPf[k * (2 * FP_STRIDE) + rl] = v;
    }
    __syncthreads();

    unsigned long long acc[4];
    acc[0] = acc[1] = acc[2] = acc[3] = 0ull;
    const int pbase = warp * 4;

    for (int kc = 0; kc < IN_F / 32; ++kc) {
        unsigned long long w2[32];
        #pragma unroll
        for (int kk = 0; kk < 32; ++kk) {
            float w = sW[(kc * 32 + kk) * OUT_F + lane];
            PACK_DUP_F32X2(w2[kk], w);
        }
        #pragma unroll
        for (int rp = 0; rp < 4; ++rp) {
            const unsigned long long* f = &sFPu[(size_t)(kc * 32) * FP_STRIDE
                                                + pbase + rp];
            #pragma unroll
            for (int kk = 0; kk < 32; ++kk) {
                unsigned long long f2 = f[kk * FP_STRIDE];   // LDS.b64 bcast
                FMA_F32X2(acc[rp], f2, w2[kk]);
            }
        }
    }

    #pragma unroll
    for (int rp = 0; rp < 4; ++rp) {
        float a0, a1;
        UNPACK_F32X2(a0, a1, acc[rp]);
        int r0 = row0 + (pbase + rp) * 2;
        if (r0 < n_nodes)
            g_h[(size_t)r0 * OUT_F + lane] = a0;
        if (r0 + 1 < n_nodes)
            g_h[(size_t)(r0 + 1) * OUT_F + lane] = a1;
    }
}

// ---------------------------------------------------------------------------
// Aggregation: warp per destination node, lane = output column.
// Applies per-source scale (broadcast LDG) + fused indeg^-1/2, bias, relu.
// Zeroes g_indeg after use (invariant restore).
__global__ void k_agg(float* __restrict__ out,
                      const float* __restrict__ bias, int n_nodes) {
    int warp = (blockIdx.x * blockDim.x + threadIdx.x) >> 5;
    int lane = threadIdx.x & 31;
    if (warp >= n_nodes) return;

    unsigned deg = g_indeg[warp];
    unsigned off = g_off[warp] + g_bsum[warp >> SCAN_SHIFT] - deg;
    if (lane == 0) g_indeg[warp] = 0u;                 // restore invariant

    float acc0 = 0.f, acc1 = 0.f;
    for (unsigned c = 0; c < deg; c += 32) {
        unsigned rem = deg - c;
        unsigned cnt = rem < 32u ? rem : 32u;
        int e = (lane < cnt) ? g_esrc[off + c + lane] : 0;
        unsigned j = 0;
        for (; j + 2 <= cnt; j += 2) {
            int s0 = __shfl_sync(0xFFFFFFFFu, e, j);
            int s1 = __shfl_sync(0xFFFFFFFFu, e, j + 1);
            float sc0 = g_scale[s0];                   // broadcast LDG
            float sc1 = g_scale[s1];
            acc0 = fmaf(g_h[(size_t)s0 * OUT_F + lane], sc0, acc0);
            acc1 = fmaf(g_h[(size_t)s1 * OUT_F + lane], sc1, acc1);
        }
        if (j < cnt) {
            int s0 = __shfl_sync(0xFFFFFFFFu, e, j);
            acc0 = fmaf(g_h[(size_t)s0 * OUT_F + lane], g_scale[s0], acc0);
        }
    }

    float sc = rsqrtf((float)(deg ? deg : 1u));
    float v = fmaf(acc0 + acc1, sc, bias[lane]);
    out[(size_t)warp * OUT_F + lane] = fmaxf(v, 0.f);
}

// ---------------------------------------------------------------------------
extern "C" void kernel_launch(void* const* d_in, const int* in_sizes, int n_in,
                              void* d_out, int out_size) {
    const float* feat = (const float*)d_in[0];
    const int*   src  = (const int*)d_in[1];
    const int*   dst  = (const int*)d_in[2];
    const float* W    = (const float*)d_in[3];
    const float* bias = (const float*)d_in[4];
    float* out = (float*)d_out;

    const int N = in_sizes[0] / IN_F;
    const int E = in_sizes[1];

    cudaFuncSetAttribute(k_gemm, cudaFuncAttributeMaxDynamicSharedMemorySize,
                         GEMM_SMEM);

    // host-only objects (no device memory)
    cudaStream_t side;
    cudaEvent_t ev_fork, ev_join;
    cudaStreamCreateWithFlags(&side, cudaStreamNonBlocking);
    cudaEventCreateWithFlags(&ev_fork, cudaEventDisableTiming);
    cudaEventCreateWithFlags(&ev_join, cudaEventDisableTiming);

    // fork side chain at t=0: gemm depends on nothing
    cudaEventRecord(ev_fork, 0);
    cudaStreamWaitEvent(side, ev_fork, 0);
    k_gemm<<<(N + TILE_R - 1) / TILE_R, 256, GEMM_SMEM, side>>>(feat, W, N);
    cudaEventRecord(ev_join, side);

    // main chain: deg -> scan -> fill
    k_deg<<<(E + 255) / 256, 256>>>(src, dst, E);
    k_scan<<<SCAN_NBLK, SCAN_BLK>>>(N);
    k_fill<<<(E + 255) / 256, 256>>>(src, dst, E);

    // join, aggregate
    cudaStreamWaitEvent(0, ev_join, 0);
    k_agg<<<(N * 32 + 255) / 256, 256>>>(out, bias, N);
}

// round 9
// speedup vs baseline: 1.4292x; 1.4114x over previous
#include <cuda_runtime.h>
#include <cstdint>

// ---------------------------------------------------------------------------
// GCN layer: out = relu( D_in^-1/2 · A · D_out^-1/2 · (X @ W) + b )
// N=100000, E=1600000, IN=256, OUT=32  (fp32, src/dst int32)
//
// Graph (R5 structure, scan+fill fused):
//   zero -> deg -> +-> gemm (side stream)        -+-> agg
//                  +-> scanfill (main, sw barrier)-+
// ---------------------------------------------------------------------------

#define NMAX 100000
#define EMAX 1600000
#define IN_F 256
#define OUT_F 32
#define SCAN_BLK 512
#define SCAN_SHIFT 9
#define SCAN_NBLK ((NMAX + SCAN_BLK - 1) / SCAN_BLK)   // 196

#define TILE_R 64
#define FP_STRIDE 33
#define GEMM_SMEM (IN_F * OUT_F * 4 + IN_F * FP_STRIDE * 8)   // 98KB

__device__ unsigned g_outdeg[NMAX];
__device__ unsigned g_indeg[NMAX];
__device__ unsigned g_off[NMAX];
__device__ unsigned g_bsum[SCAN_NBLK];
__device__ unsigned g_scan_ctr;
__device__ int      g_esrc[EMAX];
__device__ __align__(16) float g_h[(size_t)NMAX * OUT_F];

// packed f32x2 helpers -------------------------------------------------------
#define FMA_F32X2(acc, a, b) \
    asm("fma.rn.f32x2 %0, %1, %2, %0;" : "+l"(acc) : "l"(a), "l"(b))
#define PACK_DUP_F32X2(out, w) \
    asm("mov.b64 %0, {%1, %1};" : "=l"(out) : "f"(w))
#define UNPACK_F32X2(lo, hi, in) \
    asm("mov.b64 {%0, %1}, %2;" : "=f"(lo), "=f"(hi) : "l"(in))

// ---------------------------------------------------------------------------
__global__ void k_zero(int n_nodes) {
    int i = blockIdx.x * blockDim.x + threadIdx.x;
    if (i < n_nodes) {
        g_outdeg[i] = 0u;
        g_indeg[i]  = 0u;
    }
    if (i == 0) g_scan_ctr = 0u;
}

// ---------------------------------------------------------------------------
__global__ void k_deg(const int* __restrict__ src,
                      const int* __restrict__ dst, int E) {
    int i = blockIdx.x * blockDim.x + threadIdx.x;
    if (i < E) {
        atomicAdd(&g_outdeg[src[i]], 1u);
        atomicAdd(&g_indeg[dst[i]], 1u);
    }
}

// ---------------------------------------------------------------------------
// Fused scan + fill with a software global barrier.
// Phase 1: per-block scan of indeg -> g_off (block-local exclusive) + g_bsum.
// Barrier: arrivals counted on g_scan_ctr (zeroed each replay by k_zero);
//          196th arrival exclusive-scans g_bsum, then bumps ctr to 197.
// Phase 2: grid-strided CSR fill (cursor fused into g_off via atomic bump).
// No deadlock: blocks not yet resident get scheduled as gemm/other blocks
// drain; spinners use nanosleep backoff.
__global__ void k_scanfill(const int* __restrict__ src,
                           const int* __restrict__ dst,
                           int n_nodes, int E) {
    __shared__ unsigned s[SCAN_BLK];
    __shared__ bool is_last;
    int t = threadIdx.x;
    int i = blockIdx.x * SCAN_BLK + t;

    // ---- phase 1: block-local scan ----
    unsigned v = (i < n_nodes) ? g_indeg[i] : 0u;
    s[t] = v;
    __syncthreads();
    for (int off = 1; off < SCAN_BLK; off <<= 1) {
        unsigned x = (t >= off) ? s[t - off] : 0u;
        __syncthreads();
        s[t] += x;
        __syncthreads();
    }
    if (i < n_nodes) g_off[i] = s[t] - v;          // block-local exclusive
    if (t == SCAN_BLK - 1) g_bsum[blockIdx.x] = s[t];

    // ---- barrier: arrive ----
    __threadfence();
    if (t == 0) {
        unsigned done = atomicAdd(&g_scan_ctr, 1u);
        is_last = (done == (unsigned)(gridDim.x - 1));
    }
    __syncthreads();

    if (is_last) {
        // aggregate block sums (exclusive scan of g_bsum)
        unsigned bv = (t < SCAN_NBLK) ? g_bsum[t] : 0u;
        s[t] = bv;
        __syncthreads();
        for (int off = 1; off < 256; off <<= 1) {
            unsigned x = (t >= off && t < 256) ? s[t - off] : 0u;
            __syncthreads();
            if (t < 256) s[t] += x;
            __syncthreads();
        }
        if (t < SCAN_NBLK) g_bsum[t] = s[t] - bv;
        __threadfence();
        __syncthreads();
        if (t == 0) atomicAdd(&g_scan_ctr, 1u);    // release: ctr -> 197
    }

    // ---- barrier: wait for release ----
    if (t == 0) {
        while (*(volatile unsigned*)&g_scan_ctr <= (unsigned)gridDim.x)
            __nanosleep(64);
    }
    __syncthreads();
    __threadfence();

    // ---- phase 2: grid-strided CSR fill ----
    int nt = gridDim.x * SCAN_BLK;
    for (int e = blockIdx.x * SCAN_BLK + t; e < E; e += nt) {
        int d = dst[e];
        unsigned pos = atomicAdd(&g_off[d], 1u) + g_bsum[d >> SCAN_SHIFT];
        g_esrc[pos] = src[e];
    }
}

// ---------------------------------------------------------------------------
// GEMM with packed f32x2 FMA. 256 threads, 64-row tile, 98KB dynamic smem.
__global__ void __launch_bounds__(256, 2)
k_gemm(const float* __restrict__ feat, const float* __restrict__ W,
       int n_nodes) {
    extern __shared__ float smem[];
    float* sW = smem;                                    // [256][32]
    float* sFPf = smem + IN_F * OUT_F;                   // [256 k][66 floats]
    unsigned long long* sFPu = (unsigned long long*)sFPf;

    const int tid  = threadIdx.x;
    const int lane = tid & 31;
    const int warp = tid >> 5;
    const int row0 = blockIdx.x * TILE_R;

    for (int i = tid; i < (IN_F * OUT_F) / 4; i += 256)
        ((float4*)sW)[i] = ((const float4*)W)[i];

    // transpose-load feat tile (coalesced LDG.32, 2-way-conflict STS)
    for (int it = 0; it < TILE_R; ++it) {
        int idx = tid + 256 * it;          // idx = r_local*256 + k
        int rl = idx >> 8;
        int k  = idx & 255;
        int row = row0 + rl;
        float v = (row < n_nodes) ? feat[(size_t)row * IN_F + k] : 0.f;
        sFPf[k * (2 * FP_STRIDE) + rl] = v;
    }
    __syncthreads();

    unsigned long long acc[4];
    acc[0] = acc[1] = acc[2] = acc[3] = 0ull;
    const int pbase = warp * 4;                 // 4 row-pairs per warp

    for (int kc = 0; kc < IN_F / 32; ++kc) {
        unsigned long long w2[32];
        #pragma unroll
        for (int kk = 0; kk < 32; ++kk) {
            float w = sW[(kc * 32 + kk) * OUT_F + lane];
            PACK_DUP_F32X2(w2[kk], w);
        }
        #pragma unroll
        for (int rp = 0; rp < 4; ++rp) {
            const unsigned long long* f = &sFPu[(size_t)(kc * 32) * FP_STRIDE
                                                + pbase + rp];
            #pragma unroll
            for (int kk = 0; kk < 32; ++kk) {
                unsigned long long f2 = f[kk * FP_STRIDE];   // LDS.b64 bcast
                FMA_F32X2(acc[rp], f2, w2[kk]);
            }
        }
    }

    #pragma unroll
    for (int rp = 0; rp < 4; ++rp) {
        float a0, a1;
        UNPACK_F32X2(a0, a1, acc[rp]);
        int r0 = row0 + (pbase + rp) * 2;
        if (r0 < n_nodes) {
            unsigned d = g_outdeg[r0];
            g_h[(size_t)r0 * OUT_F + lane] = a0 * rsqrtf((float)(d ? d : 1u));
        }
        if (r0 + 1 < n_nodes) {
            unsigned d = g_outdeg[r0 + 1];
            g_h[(size_t)(r0 + 1) * OUT_F + lane] =
                a1 * rsqrtf((float)(d ? d : 1u));
        }
    }
}

// ---------------------------------------------------------------------------
// Aggregation: warp per destination node, lane = output column.
__global__ void k_agg(float* __restrict__ out,
                      const float* __restrict__ bias, int n_nodes) {
    int warp = (blockIdx.x * blockDim.x + threadIdx.x) >> 5;
    int lane = threadIdx.x & 31;
    if (warp >= n_nodes) return;

    unsigned deg = g_indeg[warp];
    unsigned off = g_off[warp] + g_bsum[warp >> SCAN_SHIFT] - deg;

    float acc0 = 0.f, acc1 = 0.f;
    for (unsigned c = 0; c < deg; c += 32) {
        unsigned rem = deg - c;
        unsigned cnt = rem < 32u ? rem : 32u;
        int e = (lane < cnt) ? g_esrc[off + c + lane] : 0;
        unsigned j = 0;
        for (; j + 2 <= cnt; j += 2) {
            int s0 = __shfl_sync(0xFFFFFFFFu, e, j);
            int s1 = __shfl_sync(0xFFFFFFFFu, e, j + 1);
            acc0 += g_h[(size_t)s0 * OUT_F + lane];
            acc1 += g_h[(size_t)s1 * OUT_F + lane];
        }
        if (j < cnt) {
            int s0 = __shfl_sync(0xFFFFFFFFu, e, j);
            acc0 += g_h[(size_t)s0 * OUT_F + lane];
        }
    }

    float sc = rsqrtf((float)(deg ? deg : 1u));
    float v = fmaf(acc0 + acc1, sc, bias[lane]);
    out[(size_t)warp * OUT_F + lane] = fmaxf(v, 0.f);
}

// ---------------------------------------------------------------------------
extern "C" void kernel_launch(void* const* d_in, const int* in_sizes, int n_in,
                              void* d_out, int out_size) {
    const float* feat = (const float*)d_in[0];
    const int*   src  = (const int*)d_in[1];
    const int*   dst  = (const int*)d_in[2];
    const float* W    = (const float*)d_in[3];
    const float* bias = (const float*)d_in[4];
    float* out = (float*)d_out;

    const int N = in_sizes[0] / IN_F;
    const int E = in_sizes[1];

    cudaFuncSetAttribute(k_gemm, cudaFuncAttributeMaxDynamicSharedMemorySize,
                         GEMM_SMEM);

    // host-only objects (no device memory)
    cudaStream_t side;
    cudaEvent_t ev_fork, ev_join;
    cudaStreamCreateWithFlags(&side, cudaStreamNonBlocking);
    cudaEventCreateWithFlags(&ev_fork, cudaEventDisableTiming);
    cudaEventCreateWithFlags(&ev_join, cudaEventDisableTiming);

    // main stream: zero -> deg
    k_zero<<<(N + 255) / 256, 256>>>(N);
    k_deg<<<(E + 255) / 256, 256>>>(src, dst, E);

    // fork: gemm on side stream (depends only on deg)
    cudaEventRecord(ev_fork, 0);
    cudaStreamWaitEvent(side, ev_fork, 0);
    k_gemm<<<(N + TILE_R - 1) / TILE_R, 256, GEMM_SMEM, side>>>(feat, W, N);
    cudaEventRecord(ev_join, side);

    // main: fused scan+fill (CSR build), concurrent with gemm
    k_scanfill<<<SCAN_NBLK, SCAN_BLK>>>(src, dst, N, E);

    // join, then aggregate
    cudaStreamWaitEvent(0, ev_join, 0);
    k_agg<<<(N * 32 + 255) / 256, 256>>>(out, bias, N);
}

// round 10
// speedup vs baseline: 1.5880x; 1.1111x over previous
#include <cuda_runtime.h>
#include <cstdint>

// ---------------------------------------------------------------------------
// GCN layer: out = relu( D_in^-1/2 · A · D_out^-1/2 · (X @ W) + b )
// N=100000, E=1600000, IN=256, OUT=32  (fp32, src/dst int32)
//
// Graph (R5 structure):
//   zero -> deg -> +-> gemm (side stream)   -+-> agg
//                  +-> scan -> fill (main)  -+
// ---------------------------------------------------------------------------

#define NMAX 100000
#define EMAX 1600000
#define IN_F 256
#define OUT_F 32
#define SCAN_BLK 512
#define SCAN_SHIFT 9
#define SCAN_NBLK ((NMAX + SCAN_BLK - 1) / SCAN_BLK)   // 196

#define TILE_R 64
#define FP_STRIDE 34   // float2 pairs per k-row (32 + 2 pad, EVEN for 16B align)
#define GEMM_SMEM (IN_F * OUT_F * 4 + IN_F * FP_STRIDE * 8)   // 32KB + 68KB = 100KB

__device__ unsigned g_outdeg[NMAX];
__device__ unsigned g_indeg[NMAX];
__device__ unsigned g_off[NMAX];
__device__ unsigned g_bsum[SCAN_NBLK];
__device__ unsigned g_scan_ctr;
__device__ int      g_esrc[EMAX];
__device__ __align__(16) float g_h[(size_t)NMAX * OUT_F];

// packed f32x2 helpers -------------------------------------------------------
#define FMA_F32X2(acc, a, b) \
    asm("fma.rn.f32x2 %0, %1, %2, %0;" : "+l"(acc) : "l"(a), "l"(b))
#define PACK_DUP_F32X2(out, w) \
    asm("mov.b64 %0, {%1, %1};" : "=l"(out) : "f"(w))
#define UNPACK_F32X2(lo, hi, in) \
    asm("mov.b64 {%0, %1}, %2;" : "=f"(lo), "=f"(hi) : "l"(in))

// ---------------------------------------------------------------------------
__global__ void k_zero(int n_nodes) {
    int i = blockIdx.x * blockDim.x + threadIdx.x;
    if (i < n_nodes) {
        g_outdeg[i] = 0u;
        g_indeg[i]  = 0u;
    }
    if (i == 0) g_scan_ctr = 0u;
}

// ---------------------------------------------------------------------------
__global__ void k_deg(const int* __restrict__ src,
                      const int* __restrict__ dst, int E) {
    int i = blockIdx.x * blockDim.x + threadIdx.x;
    if (i < E) {
        atomicAdd(&g_outdeg[src[i]], 1u);
        atomicAdd(&g_indeg[dst[i]], 1u);
    }
}

// ---------------------------------------------------------------------------
// Single-pass two-level scan (last-block aggregates g_bsum).
__global__ void k_scan(int n_nodes) {
    __shared__ unsigned s[SCAN_BLK];
    __shared__ bool is_last;
    int t = threadIdx.x;
    int i = blockIdx.x * SCAN_BLK + t;
    unsigned v = (i < n_nodes) ? g_indeg[i] : 0u;
    s[t] = v;
    __syncthreads();
    for (int off = 1; off < SCAN_BLK; off <<= 1) {
        unsigned x = (t >= off) ? s[t - off] : 0u;
        __syncthreads();
        s[t] += x;
        __syncthreads();
    }
    if (i < n_nodes) g_off[i] = s[t] - v;          // block-local exclusive
    if (t == SCAN_BLK - 1) g_bsum[blockIdx.x] = s[t];

    __threadfence();
    if (t == 0) {
        unsigned done = atomicAdd(&g_scan_ctr, 1u);
        is_last = (done == (unsigned)(gridDim.x - 1));
    }
    __syncthreads();
    if (is_last) {
        __threadfence();
        unsigned bv = (t < SCAN_NBLK) ? g_bsum[t] : 0u;
        s[t] = bv;
        __syncthreads();
        for (int off = 1; off < 256; off <<= 1) {
            unsigned x = (t >= off && t < 256) ? s[t - off] : 0u;
            __syncthreads();
            if (t < 256) s[t] += x;
            __syncthreads();
        }
        if (t < SCAN_NBLK) g_bsum[t] = s[t] - bv;  // exclusive block sums
    }
}

// ---------------------------------------------------------------------------
// CSR fill: 1 edge per thread, cursor fused into g_off (atomic bump).
__global__ void k_fill(const int* __restrict__ src,
                       const int* __restrict__ dst, int E) {
    int i = blockIdx.x * blockDim.x + threadIdx.x;
    if (i < E) {
        int d = dst[i];
        unsigned pos = atomicAdd(&g_off[d], 1u) + g_bsum[d >> SCAN_SHIFT];
        g_esrc[pos] = src[i];
    }
}

// ---------------------------------------------------------------------------
// GEMM, packed f32x2 FMA, LDS.128 dual-rowpair loads (halves crossbar traffic:
// 96 LDS/kc/warp instead of 160). 256 threads, 64-row tile, 100KB dyn smem.
__global__ void __launch_bounds__(256, 2)
k_gemm(const float* __restrict__ feat, const float* __restrict__ W,
       int n_nodes) {
    extern __shared__ float smem[];
    float* sW = smem;                                    // [256][32]
    float* sFPf = smem + IN_F * OUT_F;                   // [256 k][68 floats]
    unsigned long long* sFPu = (unsigned long long*)sFPf;

    const int tid  = threadIdx.x;
    const int lane = tid & 31;
    const int warp = tid >> 5;
    const int row0 = blockIdx.x * TILE_R;

    for (int i = tid; i < (IN_F * OUT_F) / 4; i += 256)
        ((float4*)sW)[i] = ((const float4*)W)[i];

    // transpose-load feat tile (coalesced LDG.32; 4-way-conflict STS, cheap)
    for (int it = 0; it < TILE_R; ++it) {
        int idx = tid + 256 * it;          // idx = r_local*256 + k
        int rl = idx >> 8;
        int k  = idx & 255;
        int row = row0 + rl;
        float v = (row < n_nodes) ? feat[(size_t)row * IN_F + k] : 0.f;
        sFPf[k * (2 * FP_STRIDE) + rl] = v;
    }
    __syncthreads();

    unsigned long long acc[4];
    acc[0] = acc[1] = acc[2] = acc[3] = 0ull;
    const int pbase = warp * 4;                 // 4 row-pairs per warp (even)

    for (int kc = 0; kc < IN_F / 32; ++kc) {
        unsigned long long w2[32];
        #pragma unroll
        for (int kk = 0; kk < 32; ++kk) {
            float w = sW[(kc * 32 + kk) * OUT_F + lane];
            PACK_DUP_F32X2(w2[kk], w);
        }
        #pragma unroll
        for (int kk = 0; kk < 32; ++kk) {
            size_t base = (size_t)(kc * 32 + kk) * FP_STRIDE + pbase;
            ulonglong2 fa = *(const ulonglong2*)&sFPu[base];       // pairs 0,1
            ulonglong2 fb = *(const ulonglong2*)&sFPu[base + 2];   // pairs 2,3
            FMA_F32X2(acc[0], fa.x, w2[kk]);
            FMA_F32X2(acc[1], fa.y, w2[kk]);
            FMA_F32X2(acc[2], fb.x, w2[kk]);
            FMA_F32X2(acc[3], fb.y, w2[kk]);
        }
    }

    #pragma unroll
    for (int rp = 0; rp < 4; ++rp) {
        float a0, a1;
        UNPACK_F32X2(a0, a1, acc[rp]);
        int r0 = row0 + (pbase + rp) * 2;
        if (r0 < n_nodes) {
            unsigned d = g_outdeg[r0];
            g_h[(size_t)r0 * OUT_F + lane] = a0 * rsqrtf((float)(d ? d : 1u));
        }
        if (r0 + 1 < n_nodes) {
            unsigned d = g_outdeg[r0 + 1];
            g_h[(size_t)(r0 + 1) * OUT_F + lane] =
                a1 * rsqrtf((float)(d ? d : 1u));
        }
    }
}

// ---------------------------------------------------------------------------
// Aggregation: warp per destination node, lane = output column, 4-deep MLP.
__global__ void k_agg(float* __restrict__ out,
                      const float* __restrict__ bias, int n_nodes) {
    int warp = (blockIdx.x * blockDim.x + threadIdx.x) >> 5;
    int lane = threadIdx.x & 31;
    if (warp >= n_nodes) return;

    unsigned deg = g_indeg[warp];
    unsigned off = g_off[warp] + g_bsum[warp >> SCAN_SHIFT] - deg;

    float acc0 = 0.f, acc1 = 0.f, acc2 = 0.f, acc3 = 0.f;
    for (unsigned c = 0; c < deg; c += 32) {
        unsigned rem = deg - c;
        unsigned cnt = rem < 32u ? rem : 32u;
        int e = (lane < cnt) ? g_esrc[off + c + lane] : 0;
        unsigned j = 0;
        for (; j + 4 <= cnt; j += 4) {
            int s0 = __shfl_sync(0xFFFFFFFFu, e, j);
            int s1 = __shfl_sync(0xFFFFFFFFu, e, j + 1);
            int s2 = __shfl_sync(0xFFFFFFFFu, e, j + 2);
            int s3 = __shfl_sync(0xFFFFFFFFu, e, j + 3);
            acc0 += g_h[(size_t)s0 * OUT_F + lane];
            acc1 += g_h[(size_t)s1 * OUT_F + lane];
            acc2 += g_h[(size_t)s2 * OUT_F + lane];
            acc3 += g_h[(size_t)s3 * OUT_F + lane];
        }
        for (; j < cnt; ++j) {
            int s0 = __shfl_sync(0xFFFFFFFFu, e, j);
            acc0 += g_h[(size_t)s0 * OUT_F + lane];
        }
    }

    float sc = rsqrtf((float)(deg ? deg : 1u));
    float v = fmaf((acc0 + acc1) + (acc2 + acc3), sc, bias[lane]);
    out[(size_t)warp * OUT_F + lane] = fmaxf(v, 0.f);
}

// ---------------------------------------------------------------------------
extern "C" void kernel_launch(void* const* d_in, const int* in_sizes, int n_in,
                              void* d_out, int out_size) {
    const float* feat = (const float*)d_in[0];
    const int*   src  = (const int*)d_in[1];
    const int*   dst  = (const int*)d_in[2];
    const float* W    = (const float*)d_in[3];
    const float* bias = (const float*)d_in[4];
    float* out = (float*)d_out;

    const int N = in_sizes[0] / IN_F;
    const int E = in_sizes[1];

    cudaFuncSetAttribute(k_gemm, cudaFuncAttributeMaxDynamicSharedMemorySize,
                         GEMM_SMEM);

    // host-only objects (no device memory)
    cudaStream_t side;
    cudaEvent_t ev_fork, ev_join;
    cudaStreamCreateWithFlags(&side, cudaStreamNonBlocking);
    cudaEventCreateWithFlags(&ev_fork, cudaEventDisableTiming);
    cudaEventCreateWithFlags(&ev_join, cudaEventDisableTiming);

    // main stream: zero -> deg
    k_zero<<<(N + 255) / 256, 256>>>(N);
    k_deg<<<(E + 255) / 256, 256>>>(src, dst, E);

    // fork: gemm on side stream (depends only on deg)
    cudaEventRecord(ev_fork, 0);
    cudaStreamWaitEvent(side, ev_fork, 0);
    k_gemm<<<(N + TILE_R - 1) / TILE_R, 256, GEMM_SMEM, side>>>(feat, W, N);
    cudaEventRecord(ev_join, side);

    // main: scan -> fill (CSR build), concurrent with gemm
    k_scan<<<SCAN_NBLK, SCAN_BLK>>>(N);
    k_fill<<<(E + 255) / 256, 256>>>(src, dst, E);

    // join, then aggregate
    cudaStreamWaitEvent(0, ev_join, 0);
    k_agg<<<(N * 32 + 255) / 256, 256>>>(out, bias, N);
}